// round 1
// baseline (speedup 1.0000x reference)
#include <cuda_runtime.h>
#include <math.h>
#include <stdint.h>

#define SEQ    4096
#define HID    768
#define NHEAD  12
#define HD     64
#define NBATCH 2
#define NOUT   2304   // 3*HID

// Scratch: y = x @ W^T + b, natural [B, S, 2304] layout.
// Per (b,h): Q = y_flat[b* S*NOUT + h*3*S*HD + 0*S*HD], contiguous [S, HD].
__device__ float g_y[NBATCH * SEQ * NOUT];

__device__ __forceinline__ float fast_exp2(float x) {
    float y;
    asm("ex2.approx.f32 %0, %1;" : "=f"(y) : "f"(x));
    return y;
}

// ---------------------------------------------------------------------------
// QKV GEMM: y[m][n] = sum_k X[m][k] * W[n][k] + bias[n]
// M = B*S = 8192, N = 2304, K = 768.  BM=BN=128, BK=8, 256 thr, 8x8/thread.
// ---------------------------------------------------------------------------
__global__ __launch_bounds__(256) void qkv_gemm(const float* __restrict__ X,
                                                const float* __restrict__ W,
                                                const float* __restrict__ bias) {
    __shared__ float Ast[8][128];   // [k][m]
    __shared__ float Bst[8][128];   // [k][n]

    const int tid = threadIdx.x;
    const int tx  = tid & 15;       // n direction
    const int ty  = tid >> 4;       // m direction
    const int mBase = blockIdx.y * 128;
    const int nBase = blockIdx.x * 128;

    const int lr = tid >> 1;            // 0..127 (tile row)
    const int lk = (tid & 1) * 4;       // 0 or 4 (k sub-offset)

    const float* Ap = X + (size_t)(mBase + lr) * HID + lk;
    const float* Bp = W + (size_t)(nBase + lr) * HID + lk;

    float4 ar = *(const float4*)Ap;
    float4 br = *(const float4*)Bp;

    float acc[8][8];
#pragma unroll
    for (int i = 0; i < 8; i++)
#pragma unroll
        for (int j = 0; j < 8; j++) acc[i][j] = 0.0f;

    for (int kt = 0; kt < 96; kt++) {
        // store current fragments (transposed)
        Ast[lk + 0][lr] = ar.x; Ast[lk + 1][lr] = ar.y;
        Ast[lk + 2][lr] = ar.z; Ast[lk + 3][lr] = ar.w;
        Bst[lk + 0][lr] = br.x; Bst[lk + 1][lr] = br.y;
        Bst[lk + 2][lr] = br.z; Bst[lk + 3][lr] = br.w;
        __syncthreads();

        // prefetch next tile into registers (hidden under compute)
        if (kt < 95) {
            ar = *(const float4*)(Ap + (kt + 1) * 8);
            br = *(const float4*)(Bp + (kt + 1) * 8);
        }

#pragma unroll
        for (int k = 0; k < 8; k++) {
            float a[8], b[8];
            *(float4*)(a + 0) = *(float4*)&Ast[k][ty * 8 + 0];
            *(float4*)(a + 4) = *(float4*)&Ast[k][ty * 8 + 4];
            *(float4*)(b + 0) = *(float4*)&Bst[k][tx * 8 + 0];
            *(float4*)(b + 4) = *(float4*)&Bst[k][tx * 8 + 4];
#pragma unroll
            for (int i = 0; i < 8; i++)
#pragma unroll
                for (int j = 0; j < 8; j++)
                    acc[i][j] = fmaf(a[i], b[j], acc[i][j]);
        }
        __syncthreads();
    }

    // epilogue: add bias, store
#pragma unroll
    for (int i = 0; i < 8; i++) {
        const size_t row = (size_t)(mBase + ty * 8 + i);
#pragma unroll
        for (int j4 = 0; j4 < 8; j4 += 4) {
            const int n = nBase + tx * 8 + j4;
            float4 o;
            o.x = acc[i][j4 + 0] + __ldg(&bias[n + 0]);
            o.y = acc[i][j4 + 1] + __ldg(&bias[n + 1]);
            o.z = acc[i][j4 + 2] + __ldg(&bias[n + 2]);
            o.w = acc[i][j4 + 3] + __ldg(&bias[n + 3]);
            *(float4*)(g_y + row * NOUT + n) = o;
        }
    }
}

// ---------------------------------------------------------------------------
// Flash attention: per block = one (b,h) and one 64-row q tile.
// S tile 64x64, online softmax, O accumulated in regs (4x4 per thread).
// smem: Qs[64][64], Ps[64][64], KV[64][68] (pad avoids tx-read conflicts)
// ---------------------------------------------------------------------------
#define KVSTRIDE 68
#define ATTN_SMEM ((4096 + 4096 + 64 * KVSTRIDE) * 4)   // 50176 bytes

__global__ __launch_bounds__(256, 2) void attn_kernel(float* __restrict__ out) {
    extern __shared__ float sm[];
    float* Qs = sm;            // [64][64]   reads are ty-broadcast
    float* Ps = sm + 4096;     // [64][64]   reads are ty-broadcast
    float* KV = sm + 8192;     // [64][68]   K phase: [k][d]; V phase: [k][d]

    const int tid = threadIdx.x;
    const int tx = tid & 15;   // d (and k-col in S) direction
    const int ty = tid >> 4;   // q direction
    const int qt = blockIdx.x;                 // 0..63
    const int b  = blockIdx.y / NHEAD;
    const int h  = blockIdx.y % NHEAD;

    const float* Qp = g_y + (size_t)b * SEQ * NOUT + (size_t)h * (3 * SEQ * HD);
    const float* Kp = Qp + SEQ * HD;
    const float* Vp = Kp + SEQ * HD;

    const float SC = 0.125f * 1.4426950408889634f;   // 1/sqrt(64) * log2(e)

    // load Q tile (prescaled): 1024 float4, 4 per thread
#pragma unroll
    for (int i = 0; i < 4; i++) {
        const int idx = tid + i * 256;
        const int r = idx >> 4;
        const int c = (idx & 15) << 2;
        float4 v = *(const float4*)(Qp + (size_t)(qt * 64 + r) * HD + c);
        v.x *= SC; v.y *= SC; v.z *= SC; v.w *= SC;
        *(float4*)(Qs + r * 64 + c) = v;
    }

    float acc[4][4];
    float m[4], l[4];
#pragma unroll
    for (int i = 0; i < 4; i++) {
        m[i] = -INFINITY; l[i] = 0.0f;
#pragma unroll
        for (int j = 0; j < 4; j++) acc[i][j] = 0.0f;
    }

    for (int kc = 0; kc < 64; kc++) {
        const float* Kc = Kp + (size_t)kc * 64 * HD;
        const float* Vc = Vp + (size_t)kc * 64 * HD;

        __syncthreads();   // protect KV/Ps from previous iteration's readers
        // load K chunk [64][64] -> KV (stride 68)
#pragma unroll
        for (int i = 0; i < 4; i++) {
            const int idx = tid + i * 256;
            const int r = idx >> 4;
            const int c = (idx & 15) << 2;
            *(float4*)(KV + r * KVSTRIDE + c) = *(const float4*)(Kc + r * HD + c);
        }
        __syncthreads();

        // S = Q * K^T  (both log2e-prescaled through Q)
        float s[4][4];
#pragma unroll
        for (int i = 0; i < 4; i++)
#pragma unroll
            for (int j = 0; j < 4; j++) s[i][j] = 0.0f;

#pragma unroll
        for (int d4 = 0; d4 < 16; d4++) {
            float4 q[4], k[4];
#pragma unroll
            for (int i = 0; i < 4; i++)
                q[i] = *(float4*)(Qs + (ty * 4 + i) * 64 + d4 * 4);
#pragma unroll
            for (int j = 0; j < 4; j++)
                k[j] = *(float4*)(KV + (tx * 4 + j) * KVSTRIDE + d4 * 4);
#pragma unroll
            for (int i = 0; i < 4; i++)
#pragma unroll
                for (int j = 0; j < 4; j++) {
                    s[i][j] = fmaf(q[i].x, k[j].x, s[i][j]);
                    s[i][j] = fmaf(q[i].y, k[j].y, s[i][j]);
                    s[i][j] = fmaf(q[i].z, k[j].z, s[i][j]);
                    s[i][j] = fmaf(q[i].w, k[j].w, s[i][j]);
                }
        }

        // online softmax (base-2), per q-row; reduce across 16 tx lanes
#pragma unroll
        for (int i = 0; i < 4; i++) {
            float rm = fmaxf(fmaxf(s[i][0], s[i][1]), fmaxf(s[i][2], s[i][3]));
#pragma unroll
            for (int off = 8; off >= 1; off >>= 1)
                rm = fmaxf(rm, __shfl_xor_sync(0xffffffffu, rm, off));
            const float mnew = fmaxf(m[i], rm);
            const float corr = fast_exp2(m[i] - mnew);
            float rs = 0.0f;
#pragma unroll
            for (int j = 0; j < 4; j++) {
                s[i][j] = fast_exp2(s[i][j] - mnew);
                rs += s[i][j];
            }
#pragma unroll
            for (int off = 8; off >= 1; off >>= 1)
                rs += __shfl_xor_sync(0xffffffffu, rs, off);
            l[i] = l[i] * corr + rs;
            m[i] = mnew;
#pragma unroll
            for (int j = 0; j < 4; j++) acc[i][j] *= corr;
        }

        // write P tile (float4, conflict-free)
#pragma unroll
        for (int i = 0; i < 4; i++) {
            float4 p; p.x = s[i][0]; p.y = s[i][1]; p.z = s[i][2]; p.w = s[i][3];
            *(float4*)(Ps + (ty * 4 + i) * 64 + tx * 4) = p;
        }
        __syncthreads();   // Ps ready; all K reads of KV complete

        // load V chunk over KV
#pragma unroll
        for (int i = 0; i < 4; i++) {
            const int idx = tid + i * 256;
            const int r = idx >> 4;
            const int c = (idx & 15) << 2;
            *(float4*)(KV + r * KVSTRIDE + c) = *(const float4*)(Vc + r * HD + c);
        }
        __syncthreads();

        // O += P * V
#pragma unroll
        for (int k4 = 0; k4 < 16; k4++) {
            float4 p[4], v[4];
#pragma unroll
            for (int i = 0; i < 4; i++)
                p[i] = *(float4*)(Ps + (ty * 4 + i) * 64 + k4 * 4);
#pragma unroll
            for (int kk = 0; kk < 4; kk++)
                v[kk] = *(float4*)(KV + (k4 * 4 + kk) * KVSTRIDE + tx * 4);
#pragma unroll
            for (int i = 0; i < 4; i++) {
#pragma unroll
                for (int j = 0; j < 4; j++) {
                    const float* vj = &v[0].x;  // not used; explicit below
                }
                acc[i][0] = fmaf(p[i].x, v[0].x, acc[i][0]);
                acc[i][1] = fmaf(p[i].x, v[0].y, acc[i][1]);
                acc[i][2] = fmaf(p[i].x, v[0].z, acc[i][2]);
                acc[i][3] = fmaf(p[i].x, v[0].w, acc[i][3]);
                acc[i][0] = fmaf(p[i].y, v[1].x, acc[i][0]);
                acc[i][1] = fmaf(p[i].y, v[1].y, acc[i][1]);
                acc[i][2] = fmaf(p[i].y, v[1].z, acc[i][2]);
                acc[i][3] = fmaf(p[i].y, v[1].w, acc[i][3]);
                acc[i][0] = fmaf(p[i].z, v[2].x, acc[i][0]);
                acc[i][1] = fmaf(p[i].z, v[2].y, acc[i][1]);
                acc[i][2] = fmaf(p[i].z, v[2].z, acc[i][2]);
                acc[i][3] = fmaf(p[i].z, v[2].w, acc[i][3]);
                acc[i][0] = fmaf(p[i].w, v[3].x, acc[i][0]);
                acc[i][1] = fmaf(p[i].w, v[3].y, acc[i][1]);
                acc[i][2] = fmaf(p[i].w, v[3].z, acc[i][2]);
                acc[i][3] = fmaf(p[i].w, v[3].w, acc[i][3]);
            }
        }
    }

    // epilogue: divide by l, write out[b][q][h*64 + d]
#pragma unroll
    for (int i = 0; i < 4; i++) {
        const float inv = 1.0f / l[i];
        const int q = qt * 64 + ty * 4 + i;
        float4 o;
        o.x = acc[i][0] * inv; o.y = acc[i][1] * inv;
        o.z = acc[i][2] * inv; o.w = acc[i][3] * inv;
        *(float4*)(out + (size_t)b * SEQ * HID + (size_t)q * HID + h * HD + tx * 4) = o;
    }
}

// ---------------------------------------------------------------------------
extern "C" void kernel_launch(void* const* d_in, const int* in_sizes, int n_in,
                              void* d_out, int out_size) {
    const float* x    = (const float*)d_in[0];
    const float* W    = (const float*)d_in[1];
    const float* bias = (const float*)d_in[2];
    float* out = (float*)d_out;

    // >48KB dynamic smem opt-in (host-side API; not part of the captured graph)
    cudaFuncSetAttribute(attn_kernel,
                         cudaFuncAttributeMaxDynamicSharedMemorySize, ATTN_SMEM);

    qkv_gemm<<<dim3(NOUT / 128, (NBATCH * SEQ) / 128), 256>>>(x, W, bias);
    attn_kernel<<<dim3(SEQ / 64, NBATCH * NHEAD), 256, ATTN_SMEM>>>(out);
}

// round 2
// speedup vs baseline: 1.5957x; 1.5957x over previous
#include <cuda_runtime.h>
#include <math.h>
#include <stdint.h>

#define SEQ    4096
#define HID    768
#define NHEAD  12
#define HD     64
#define NBATCH 2
#define NOUT   2304   // 3*HID

// Scratch: y = x @ W^T + b, natural [B, S, 2304] layout.
// Per (b,h): Q = y_flat[b*S*NOUT + h*3*S*HD], contiguous [S, HD]; K, V follow.
__device__ float g_y[NBATCH * SEQ * NOUT];

__device__ __forceinline__ float fast_exp2(float x) {
    float y;
    asm("ex2.approx.f32 %0, %1;" : "=f"(y) : "f"(x));
    return y;
}

// ---------------------------------------------------------------------------
// QKV GEMM: y[m][n] = sum_k X[m][k] * W[n][k] + bias[n]
// M = B*S = 8192, N = 2304, K = 768.  BM=BN=128, BK=8, 256 thr, 8x8/thread.
// ---------------------------------------------------------------------------
__global__ __launch_bounds__(256) void qkv_gemm(const float* __restrict__ X,
                                                const float* __restrict__ W,
                                                const float* __restrict__ bias) {
    __shared__ float Ast[8][128];   // [k][m]
    __shared__ float Bst[8][128];   // [k][n]

    const int tid = threadIdx.x;
    const int tx  = tid & 15;       // n direction
    const int ty  = tid >> 4;       // m direction
    const int mBase = blockIdx.y * 128;
    const int nBase = blockIdx.x * 128;

    const int lr = tid >> 1;            // 0..127 (tile row)
    const int lk = (tid & 1) * 4;       // 0 or 4 (k sub-offset)

    const float* Ap = X + (size_t)(mBase + lr) * HID + lk;
    const float* Bp = W + (size_t)(nBase + lr) * HID + lk;

    float4 ar = *(const float4*)Ap;
    float4 br = *(const float4*)Bp;

    float acc[8][8];
#pragma unroll
    for (int i = 0; i < 8; i++)
#pragma unroll
        for (int j = 0; j < 8; j++) acc[i][j] = 0.0f;

    for (int kt = 0; kt < 96; kt++) {
        Ast[lk + 0][lr] = ar.x; Ast[lk + 1][lr] = ar.y;
        Ast[lk + 2][lr] = ar.z; Ast[lk + 3][lr] = ar.w;
        Bst[lk + 0][lr] = br.x; Bst[lk + 1][lr] = br.y;
        Bst[lk + 2][lr] = br.z; Bst[lk + 3][lr] = br.w;
        __syncthreads();

        if (kt < 95) {
            ar = *(const float4*)(Ap + (kt + 1) * 8);
            br = *(const float4*)(Bp + (kt + 1) * 8);
        }

#pragma unroll
        for (int k = 0; k < 8; k++) {
            float a[8], b[8];
            *(float4*)(a + 0) = *(float4*)&Ast[k][ty * 8 + 0];
            *(float4*)(a + 4) = *(float4*)&Ast[k][ty * 8 + 4];
            *(float4*)(b + 0) = *(float4*)&Bst[k][tx * 8 + 0];
            *(float4*)(b + 4) = *(float4*)&Bst[k][tx * 8 + 4];
#pragma unroll
            for (int i = 0; i < 8; i++)
#pragma unroll
                for (int j = 0; j < 8; j++)
                    acc[i][j] = fmaf(a[i], b[j], acc[i][j]);
        }
        __syncthreads();
    }

#pragma unroll
    for (int i = 0; i < 8; i++) {
        const size_t row = (size_t)(mBase + ty * 8 + i);
#pragma unroll
        for (int j4 = 0; j4 < 8; j4 += 4) {
            const int n = nBase + tx * 8 + j4;
            float4 o;
            o.x = acc[i][j4 + 0] + __ldg(&bias[n + 0]);
            o.y = acc[i][j4 + 1] + __ldg(&bias[n + 1]);
            o.z = acc[i][j4 + 2] + __ldg(&bias[n + 2]);
            o.w = acc[i][j4 + 3] + __ldg(&bias[n + 3]);
            *(float4*)(g_y + row * NOUT + n) = o;
        }
    }
}

// ---------------------------------------------------------------------------
// Flash attention: per block = one (b,h) and one 64-row q tile.
// Thread (tx,ty): S rows ty*4+i, S cols tx+16*j  (strided cols -> LDS of K
// fragments is bank-conflict-free: group = (tx+16j)*17 + d4 = tx+d4 mod 8).
// smem: Qs[64][64], Ps[64][64], Ks[64][68], Vs[64][68].  3 syncs/iter.
// ---------------------------------------------------------------------------
#define KVSTRIDE 68
#define ATTN_SMEM ((4096 + 4096 + 2 * 64 * KVSTRIDE) * 4)   // 67584 bytes

__global__ __launch_bounds__(256, 2) void attn_kernel(float* __restrict__ out) {
    extern __shared__ float sm[];
    float* Qs = sm;                     // [64][64]  reads ty-broadcast
    float* Ps = sm + 4096;              // [64][64]  reads ty-broadcast
    float* Ks = sm + 8192;              // [64][68]
    float* Vs = Ks + 64 * KVSTRIDE;     // [64][68]

    const int tid = threadIdx.x;
    const int tx = tid & 15;   // col-group direction
    const int ty = tid >> 4;   // q direction
    const int qt = blockIdx.x;                 // 0..63
    const int b  = blockIdx.y / NHEAD;
    const int h  = blockIdx.y % NHEAD;

    const float* Qp = g_y + (size_t)b * SEQ * NOUT + (size_t)h * (3 * SEQ * HD);
    const float* Kp = Qp + SEQ * HD;
    const float* Vp = Kp + SEQ * HD;

    const float SC = 0.125f * 1.4426950408889634f;   // 1/sqrt(64) * log2(e)

    // load Q tile (prescaled by SC): 1024 float4, 4 per thread
#pragma unroll
    for (int i = 0; i < 4; i++) {
        const int idx = tid + i * 256;
        const int r = idx >> 4;
        const int c = (idx & 15) << 2;
        float4 v = *(const float4*)(Qp + (size_t)(qt * 64 + r) * HD + c);
        v.x *= SC; v.y *= SC; v.z *= SC; v.w *= SC;
        *(float4*)(Qs + r * 64 + c) = v;
    }

    float acc[4][4];
    float m[4], l[4];
#pragma unroll
    for (int i = 0; i < 4; i++) {
        m[i] = -INFINITY; l[i] = 0.0f;
#pragma unroll
        for (int j = 0; j < 4; j++) acc[i][j] = 0.0f;
    }

    for (int kc = 0; kc < 64; kc++) {
        const float* Kc = Kp + (size_t)kc * 64 * HD;
        const float* Vc = Vp + (size_t)kc * 64 * HD;

        __syncthreads();   // previous iter's PV reads of Vs/Ps complete
        // load K and V chunks [64][64] -> stride-68 buffers
#pragma unroll
        for (int i = 0; i < 4; i++) {
            const int idx = tid + i * 256;
            const int r = idx >> 4;
            const int c = (idx & 15) << 2;
            *(float4*)(Ks + r * KVSTRIDE + c) = *(const float4*)(Kc + r * HD + c);
            *(float4*)(Vs + r * KVSTRIDE + c) = *(const float4*)(Vc + r * HD + c);
        }
        __syncthreads();   // K,V ready

        // S = Q * K^T ; thread col j -> key row (tx + 16*j)
        float s[4][4];
#pragma unroll
        for (int i = 0; i < 4; i++)
#pragma unroll
            for (int j = 0; j < 4; j++) s[i][j] = 0.0f;

#pragma unroll
        for (int d4 = 0; d4 < 16; d4++) {
            float4 q[4], k[4];
#pragma unroll
            for (int i = 0; i < 4; i++)
                q[i] = *(float4*)(Qs + (ty * 4 + i) * 64 + d4 * 4);
#pragma unroll
            for (int j = 0; j < 4; j++)
                k[j] = *(float4*)(Ks + (tx + 16 * j) * KVSTRIDE + d4 * 4);
#pragma unroll
            for (int i = 0; i < 4; i++)
#pragma unroll
                for (int j = 0; j < 4; j++) {
                    s[i][j] = fmaf(q[i].x, k[j].x, s[i][j]);
                    s[i][j] = fmaf(q[i].y, k[j].y, s[i][j]);
                    s[i][j] = fmaf(q[i].z, k[j].z, s[i][j]);
                    s[i][j] = fmaf(q[i].w, k[j].w, s[i][j]);
                }
        }

        // online softmax (base-2), per q-row; reduce across 16 tx lanes
#pragma unroll
        for (int i = 0; i < 4; i++) {
            float rm = fmaxf(fmaxf(s[i][0], s[i][1]), fmaxf(s[i][2], s[i][3]));
#pragma unroll
            for (int off = 8; off >= 1; off >>= 1)
                rm = fmaxf(rm, __shfl_xor_sync(0xffffffffu, rm, off));
            const float mnew = fmaxf(m[i], rm);
            const float corr = fast_exp2(m[i] - mnew);
            float rs = 0.0f;
#pragma unroll
            for (int j = 0; j < 4; j++) {
                s[i][j] = fast_exp2(s[i][j] - mnew);
                rs += s[i][j];
            }
#pragma unroll
            for (int off = 8; off >= 1; off >>= 1)
                rs += __shfl_xor_sync(0xffffffffu, rs, off);
            l[i] = l[i] * corr + rs;
            m[i] = mnew;
#pragma unroll
            for (int j = 0; j < 4; j++) acc[i][j] *= corr;
        }

        // write P tile (scalar, col = tx + 16*j; 2-way write conflict max)
#pragma unroll
        for (int i = 0; i < 4; i++)
#pragma unroll
            for (int j = 0; j < 4; j++)
                Ps[(ty * 4 + i) * 64 + tx + 16 * j] = s[i][j];
        __syncthreads();   // Ps ready

        // O += P * V  (p reads ty-broadcast; v reads conflict-free)
#pragma unroll
        for (int k4 = 0; k4 < 16; k4++) {
            float4 p[4], v[4];
#pragma unroll
            for (int i = 0; i < 4; i++)
                p[i] = *(float4*)(Ps + (ty * 4 + i) * 64 + k4 * 4);
#pragma unroll
            for (int kk = 0; kk < 4; kk++)
                v[kk] = *(float4*)(Vs + (k4 * 4 + kk) * KVSTRIDE + tx * 4);
#pragma unroll
            for (int i = 0; i < 4; i++) {
                acc[i][0] = fmaf(p[i].x, v[0].x, acc[i][0]);
                acc[i][1] = fmaf(p[i].x, v[0].y, acc[i][1]);
                acc[i][2] = fmaf(p[i].x, v[0].z, acc[i][2]);
                acc[i][3] = fmaf(p[i].x, v[0].w, acc[i][3]);
                acc[i][0] = fmaf(p[i].y, v[1].x, acc[i][0]);
                acc[i][1] = fmaf(p[i].y, v[1].y, acc[i][1]);
                acc[i][2] = fmaf(p[i].y, v[1].z, acc[i][2]);
                acc[i][3] = fmaf(p[i].y, v[1].w, acc[i][3]);
                acc[i][0] = fmaf(p[i].z, v[2].x, acc[i][0]);
                acc[i][1] = fmaf(p[i].z, v[2].y, acc[i][1]);
                acc[i][2] = fmaf(p[i].z, v[2].z, acc[i][2]);
                acc[i][3] = fmaf(p[i].z, v[2].w, acc[i][3]);
                acc[i][0] = fmaf(p[i].w, v[3].x, acc[i][0]);
                acc[i][1] = fmaf(p[i].w, v[3].y, acc[i][1]);
                acc[i][2] = fmaf(p[i].w, v[3].z, acc[i][2]);
                acc[i][3] = fmaf(p[i].w, v[3].w, acc[i][3]);
            }
        }
    }

    // epilogue: divide by l, write out[b][q][h*64 + d]  (d = tx*4 .. tx*4+3)
#pragma unroll
    for (int i = 0; i < 4; i++) {
        const float inv = 1.0f / l[i];
        const int q = qt * 64 + ty * 4 + i;
        float4 o;
        o.x = acc[i][0] * inv; o.y = acc[i][1] * inv;
        o.z = acc[i][2] * inv; o.w = acc[i][3] * inv;
        *(float4*)(out + (size_t)b * SEQ * HID + (size_t)q * HID + h * HD + tx * 4) = o;
    }
}

// ---------------------------------------------------------------------------
extern "C" void kernel_launch(void* const* d_in, const int* in_sizes, int n_in,
                              void* d_out, int out_size) {
    const float* x    = (const float*)d_in[0];
    const float* W    = (const float*)d_in[1];
    const float* bias = (const float*)d_in[2];
    float* out = (float*)d_out;

    cudaFuncSetAttribute(attn_kernel,
                         cudaFuncAttributeMaxDynamicSharedMemorySize, ATTN_SMEM);

    qkv_gemm<<<dim3(NOUT / 128, (NBATCH * SEQ) / 128), 256>>>(x, W, bias);
    attn_kernel<<<dim3(SEQ / 64, NBATCH * NHEAD), 256, ATTN_SMEM>>>(out);
}